// round 4
// baseline (speedup 1.0000x reference)
#include <cuda_runtime.h>
#include <math.h>

// VanillaRNN: h_{t+1} = tanh(x[:,t]*W_hx^T + b_hx + h_t @ W_hh^T + b_hh), 1024 steps,
// then softmax(h @ W_oh^T + b_oh). Persistent kernel, one grid barrier per step.

#define GX 16      // column blocks (512 / 32)
#define GY 8       // row blocks    (512 / 64)
#define NCTA (GX*GY)
#define NTHR 256

constexpr int B = 512, S = 1024, H = 512, OUTD = 10;
constexpr int BM = 64, BN = 32, KC = 64;
constexpr int NCHUNK = H / KC;          // 8
constexpr int WS_STRIDE = 36;           // padded stride for W tile (bank-conflict-free, float2-aligned)
constexpr int HS_STRIDE = 65;           // padded stride for h chunk (bank-conflict-free)
constexpr int SMEM_FLOATS = H * WS_STRIDE + 2 * KC * HS_STRIDE;
constexpr int SMEM_BYTES = SMEM_FLOATS * 4;   // 107008 B

// ping-pong hidden state, 2 MB static (allocation-free rule)
__device__ __align__(16) float g_h[2][B * H];
__device__ unsigned g_arrive = 0;
__device__ unsigned g_phase  = 0;

// Phase-exact grid barrier. Completer resets arrive counter, then publishes phase v.
// The run's last barrier publishes 0, restoring initial state for the next replay.
__device__ __forceinline__ void grid_barrier(unsigned v) {
    __syncthreads();
    if (threadIdx.x == 0) {
        __threadfence();
        unsigned prev = atomicAdd(&g_arrive, 1u);
        if (prev == (unsigned)(NCTA - 1)) {
            *(volatile unsigned*)&g_arrive = 0u;
            __threadfence();
            *(volatile unsigned*)&g_phase = v;
        } else {
            while (*(volatile unsigned*)&g_phase != v) { }
        }
        __threadfence();
    }
    __syncthreads();
}

__global__ void __launch_bounds__(NTHR, 1)
rnn_kernel(const float* __restrict__ x,    const float* __restrict__ W_hx,
           const float* __restrict__ b_hx, const float* __restrict__ W_hh,
           const float* __restrict__ b_hh, const float* __restrict__ W_oh,
           const float* __restrict__ b_oh, float* __restrict__ out)
{
    extern __shared__ float sm[];
    float* ws = sm;                       // [512][36] : ws[k*36 + jl], W_hh[(col0+jl)][k]
    float* hs = sm + H * WS_STRIDE;       // [2][64][65] : hs[buf][kk*65 + rl]

    const int tid  = threadIdx.x;
    const int cb   = blockIdx.x;          // 0..15
    const int rb   = blockIdx.y;          // 0..7
    const int row0 = rb * BM;
    const int col0 = cb * BN;
    const int cg   = tid & 15;            // 2 output cols: col0 + cg*2 + {0,1}
    const int rg   = tid >> 4;            // 4 output rows: row0 + rg*4 + {0..3}
    const int lf   = tid & 15;            // loader: float4 index within 64-float k-chunk
    const int lr0  = tid >> 4;            // loader: row base (rows lr0 + 16*i)

    // Load W_hh tile (fixed for all 1024 steps) into SMEM, transposed with padding.
    for (int idx = tid; idx < BN * H; idx += NTHR) {
        int jl = idx >> 9;                // 0..31
        int k  = idx & (H - 1);           // coalesced along k
        ws[k * WS_STRIDE + jl] = W_hh[(col0 + jl) * H + k];
    }
    // Per-thread column constants (input projection weight + combined bias).
    float wx0, wx1, bb0, bb1;
    {
        int j0 = col0 + cg * 2;
        wx0 = W_hx[j0];     wx1 = W_hx[j0 + 1];
        bb0 = b_hx[j0]     + b_hh[j0];
        bb1 = b_hx[j0 + 1] + b_hh[j0 + 1];
    }
    // Zero this CTA's region of h buffer 0 (h0 = zeros).
    for (int idx = tid; idx < BM * BN; idx += NTHR) {
        int rl = idx >> 5, jl = idx & 31;
        g_h[0][(row0 + rl) * H + col0 + jl] = 0.0f;
    }
    grid_barrier(1u);

    for (int t = 0; t < S; ++t) {
        const float* hin  = g_h[t & 1];
        float*       hout = g_h[(t + 1) & 1];

        // Prologue: stage chunk 0 into smem buffer 0 (transposed).
        float4 pf[4];
        #pragma unroll
        for (int i = 0; i < 4; ++i)
            pf[i] = *(const float4*)(hin + (row0 + lr0 + i * 16) * H + lf * 4);
        #pragma unroll
        for (int i = 0; i < 4; ++i) {
            int rl = lr0 + i * 16;
            hs[(lf * 4 + 0) * HS_STRIDE + rl] = pf[i].x;
            hs[(lf * 4 + 1) * HS_STRIDE + rl] = pf[i].y;
            hs[(lf * 4 + 2) * HS_STRIDE + rl] = pf[i].z;
            hs[(lf * 4 + 3) * HS_STRIDE + rl] = pf[i].w;
        }

        float a00 = 0.f, a01 = 0.f, a10 = 0.f, a11 = 0.f;
        float a20 = 0.f, a21 = 0.f, a30 = 0.f, a31 = 0.f;

        #pragma unroll 1
        for (int c = 0; c < NCHUNK; ++c) {
            __syncthreads();              // chunk c staged in hs[c&1]
            if (c + 1 < NCHUNK) {         // prefetch next chunk from L2 (hidden under compute)
                #pragma unroll
                for (int i = 0; i < 4; ++i)
                    pf[i] = *(const float4*)(hin + (row0 + lr0 + i * 16) * H
                                             + (c + 1) * KC + lf * 4);
            }
            const float* wk = ws + c * KC * WS_STRIDE + cg * 2;
            const float* hk = hs + (c & 1) * (KC * HS_STRIDE) + rg * 4;
            #pragma unroll 8
            for (int kk = 0; kk < KC; ++kk) {
                float2 wv = *(const float2*)(wk + kk * WS_STRIDE);
                float h0 = hk[kk * HS_STRIDE + 0];
                float h1 = hk[kk * HS_STRIDE + 1];
                float h2 = hk[kk * HS_STRIDE + 2];
                float h3 = hk[kk * HS_STRIDE + 3];
                a00 += h0 * wv.x;  a01 += h0 * wv.y;
                a10 += h1 * wv.x;  a11 += h1 * wv.y;
                a20 += h2 * wv.x;  a21 += h2 * wv.y;
                a30 += h3 * wv.x;  a31 += h3 * wv.y;
            }
            if (c + 1 < NCHUNK) {
                __syncthreads();          // everyone done reading hs[(c+1)&1] (used 2 chunks ago)
                float* hnx = hs + ((c + 1) & 1) * (KC * HS_STRIDE);
                #pragma unroll
                for (int i = 0; i < 4; ++i) {
                    int rl = lr0 + i * 16;
                    hnx[(lf * 4 + 0) * HS_STRIDE + rl] = pf[i].x;
                    hnx[(lf * 4 + 1) * HS_STRIDE + rl] = pf[i].y;
                    hnx[(lf * 4 + 2) * HS_STRIDE + rl] = pf[i].z;
                    hnx[(lf * 4 + 3) * HS_STRIDE + rl] = pf[i].w;
                }
            }
        }

        // Per-step epilogue: add input projection + biases, tanh, write next h.
        float xv0 = x[(row0 + rg * 4 + 0) * S + t];
        float xv1 = x[(row0 + rg * 4 + 1) * S + t];
        float xv2 = x[(row0 + rg * 4 + 2) * S + t];
        float xv3 = x[(row0 + rg * 4 + 3) * S + t];
        float* op = hout + col0 + cg * 2;
        float2 o0, o1, o2, o3;
        o0.x = tanhf(a00 + xv0 * wx0 + bb0);  o0.y = tanhf(a01 + xv0 * wx1 + bb1);
        o1.x = tanhf(a10 + xv1 * wx0 + bb0);  o1.y = tanhf(a11 + xv1 * wx1 + bb1);
        o2.x = tanhf(a20 + xv2 * wx0 + bb0);  o2.y = tanhf(a21 + xv2 * wx1 + bb1);
        o3.x = tanhf(a30 + xv3 * wx0 + bb0);  o3.y = tanhf(a31 + xv3 * wx1 + bb1);
        *(float2*)(op + (row0 + rg * 4 + 0) * H) = o0;
        *(float2*)(op + (row0 + rg * 4 + 1) * H) = o1;
        *(float2*)(op + (row0 + rg * 4 + 2) * H) = o2;
        *(float2*)(op + (row0 + rg * 4 + 3) * H) = o3;

        grid_barrier(t == S - 1 ? 0u : (unsigned)(t + 2));
    }

    // Final projection + softmax: col-block-0 CTAs handle their 64 rows.
    if (cb == 0) {
        for (int idx = tid; idx < OUTD * H; idx += NTHR) sm[idx] = W_oh[idx];
        __syncthreads();
        const float* hfin = g_h[0];       // final h lives in buffer 0 (S even)
        int r = tid >> 2, q = tid & 3;    // 4 threads per row, 128 k each
        float p[OUTD];
        #pragma unroll
        for (int c2 = 0; c2 < OUTD; ++c2) p[c2] = 0.f;
        const float* hr = hfin + (row0 + r) * H + q * 128;
        for (int k = 0; k < 128; k += 4) {
            float4 hv = *(const float4*)(hr + k);
            #pragma unroll
            for (int c2 = 0; c2 < OUTD; ++c2) {
                const float* wr = sm + c2 * H + q * 128 + k;
                p[c2] += hv.x * wr[0] + hv.y * wr[1] + hv.z * wr[2] + hv.w * wr[3];
            }
        }
        float* part = sm + OUTD * H;      // disjoint scratch region
        #pragma unroll
        for (int c2 = 0; c2 < OUTD; ++c2) part[tid * OUTD + c2] = p[c2];
        __syncthreads();
        if (tid < 64) {
            float o[OUTD];
            #pragma unroll
            for (int c2 = 0; c2 < OUTD; ++c2)
                o[c2] = part[(tid * 4 + 0) * OUTD + c2] + part[(tid * 4 + 1) * OUTD + c2]
                      + part[(tid * 4 + 2) * OUTD + c2] + part[(tid * 4 + 3) * OUTD + c2]
                      + b_oh[c2];
            float m = o[0];
            #pragma unroll
            for (int c2 = 1; c2 < OUTD; ++c2) m = fmaxf(m, o[c2]);
            float ssum = 0.f;
            #pragma unroll
            for (int c2 = 0; c2 < OUTD; ++c2) { o[c2] = expf(o[c2] - m); ssum += o[c2]; }
            float inv = 1.0f / ssum;
            #pragma unroll
            for (int c2 = 0; c2 < OUTD; ++c2)
                out[(row0 + tid) * OUTD + c2] = o[c2] * inv;
        }
    }
}

extern "C" void kernel_launch(void* const* d_in, const int* in_sizes, int n_in,
                              void* d_out, int out_size) {
    const float* x    = (const float*)d_in[0];
    const float* W_hx = (const float*)d_in[1];
    const float* b_hx = (const float*)d_in[2];
    const float* W_hh = (const float*)d_in[3];
    const float* b_hh = (const float*)d_in[4];
    const float* W_oh = (const float*)d_in[5];
    const float* b_oh = (const float*)d_in[6];
    float* out = (float*)d_out;

    cudaFuncSetAttribute(rnn_kernel, cudaFuncAttributeMaxDynamicSharedMemorySize, SMEM_BYTES);
    rnn_kernel<<<dim3(GX, GY, 1), NTHR, SMEM_BYTES>>>(x, W_hx, b_hx, W_hh, b_hh, W_oh, b_oh, out);
}

// round 5
// speedup vs baseline: 1.2125x; 1.2125x over previous
#include <cuda_runtime.h>
#include <math.h>

// VanillaRNN persistent kernel, v2:
//  - hidden state kept TRANSPOSED in gmem (hT[col][row]) -> transpose-free smem staging
//  - k split across two warp-groups, 8x2 microtile, fma.rn.f32x2 packed math
//  - one grid barrier per timestep

#define GX 16      // column blocks (512 / 32)
#define GY 8       // row blocks    (512 / 64)
#define NCTA (GX*GY)
#define NTHR 256

constexpr int Bsz = 512, S = 1024, H = 512, OUTD = 10;
constexpr int BM = 64, BN = 32;
constexpr int KC = 32;                 // k per chunk PER HALF
constexpr int NCHUNK = 8;              // 256 / 32
constexpr int WS_STRIDE = 34;          // W tile stride (LDS.64-aligned, conflict-free)
constexpr int HS_STRIDE = 68;          // h stage stride (16B-aligned, conflict-free)
constexpr int WS_FLOATS = H * WS_STRIDE;                 // 17408
constexpr int HS_FLOATS = 2 * 2 * KC * HS_STRIDE;        // 8704 (2 buf x 2 half)
constexpr int SMEM_BYTES = (WS_FLOATS + HS_FLOATS) * 4;  // 104448 B

// ping-pong TRANSPOSED hidden state hT[c][r], 2 MB static
__device__ __align__(16) float g_hT[2][H * Bsz];
__device__ unsigned g_arrive = 0;
__device__ unsigned g_phase  = 0;

// Phase-exact grid barrier; last barrier of the run publishes 0 (replay-safe).
__device__ __forceinline__ void grid_barrier(unsigned v) {
    __syncthreads();
    if (threadIdx.x == 0) {
        __threadfence();
        unsigned prev = atomicAdd(&g_arrive, 1u);
        if (prev == (unsigned)(NCTA - 1)) {
            *(volatile unsigned*)&g_arrive = 0u;
            __threadfence();
            *(volatile unsigned*)&g_phase = v;
        } else {
            while (*(volatile unsigned*)&g_phase != v) { }
        }
        __threadfence();
    }
    __syncthreads();
}

__global__ void __launch_bounds__(NTHR, 1)
rnn_kernel(const float* __restrict__ x,    const float* __restrict__ W_hx,
           const float* __restrict__ b_hx, const float* __restrict__ W_hh,
           const float* __restrict__ b_hh, const float* __restrict__ W_oh,
           const float* __restrict__ b_oh, float* __restrict__ out)
{
    extern __shared__ float sm[];
    float* ws = sm;                       // ws[k*34 + jl] = W_hh[(col0+jl)][k]
    float* hs = sm + WS_FLOATS;           // hs[buf][half][kl][r], r contiguous
    const unsigned hs_u32 = (unsigned)__cvta_generic_to_shared(hs);

    const int tid  = threadIdx.x;
    const int cb   = blockIdx.x;          // 0..15
    const int rb   = blockIdx.y;          // 0..7
    const int row0 = rb * BM;
    const int col0 = cb * BN;
    // compute roles: k-half, 2 cols, 8 rows per thread
    const int kh = tid >> 7;              // 0/1 -> k in [kh*256, kh*256+256)
    const int cg = tid & 15;              // cols col0 + 2cg + {0,1}
    const int rg = (tid >> 4) & 7;        // rows row0 + 8rg + {0..7}
    // staging roles
    const int rf = tid & 15;              // float4 index along rows (16 per k-row)
    const int kr = tid >> 4;              // k-row base (adds 16*i)

    // Load W_hh tile (constant across all steps), transposed, padded.
    for (int idx = tid; idx < BN * H; idx += NTHR) {
        int jl = idx >> 9, k = idx & (H - 1);
        ws[k * WS_STRIDE + jl] = W_hh[(col0 + jl) * H + k];
    }
    float wx0, wx1, bb0, bb1;
    {
        int j0 = col0 + cg * 2;
        wx0 = W_hx[j0];     wx1 = W_hx[j0 + 1];
        bb0 = b_hx[j0]     + b_hh[j0];
        bb1 = b_hx[j0 + 1] + b_hh[j0 + 1];
    }
    // h0 = zeros (transposed layout)
    for (int idx = tid; idx < BN * BM; idx += NTHR) {
        int jl = idx >> 6, rl = idx & 63;
        g_hT[0][(col0 + jl) * Bsz + row0 + rl] = 0.0f;
    }
    grid_barrier(1u);

    const unsigned hk_u = hs_u32 + ((unsigned)(kh * (KC * HS_STRIDE)) + (unsigned)(rg * 8)) * 4u;

    for (int t = 0; t < S; ++t) {
        const float* hin  = g_hT[t & 1];
        float*       hout = g_hT[(t + 1) & 1];

        // stage chunk 0 -> buf 0 (both halves), no transpose needed
        float4 pf[4];
        #pragma unroll
        for (int i = 0; i < 4; ++i) {
            int krow = kr + i * 16;
            int half = krow >> 5, kl = krow & 31;
            int kg = half * 256 + kl;
            pf[i] = *(const float4*)(hin + kg * Bsz + row0 + rf * 4);
        }
        #pragma unroll
        for (int i = 0; i < 4; ++i) {
            int krow = kr + i * 16;
            int half = krow >> 5, kl = krow & 31;
            *(float4*)(hs + half * (KC * HS_STRIDE) + kl * HS_STRIDE + rf * 4) = pf[i];
        }

        unsigned long long a0[4] = {0,0,0,0}, a1[4] = {0,0,0,0};

        #pragma unroll 1
        for (int c = 0; c < NCHUNK; ++c) {
            __syncthreads();              // chunk c visible in buf c&1
            if (c + 1 < NCHUNK) {         // prefetch next chunk from L2
                #pragma unroll
                for (int i = 0; i < 4; ++i) {
                    int krow = kr + i * 16;
                    int half = krow >> 5, kl = krow & 31;
                    int kg = half * 256 + (c + 1) * KC + kl;
                    pf[i] = *(const float4*)(hin + kg * Bsz + row0 + rf * 4);
                }
            }
            const float* wk = ws + (kh * 256 + c * KC) * WS_STRIDE + 2 * cg;
            const unsigned hb = hk_u + (unsigned)((c & 1) * (2 * KC * HS_STRIDE)) * 4u;
            #pragma unroll 8
            for (int kk = 0; kk < KC; ++kk) {
                float2 wv = *(const float2*)(wk + kk * WS_STRIDE);
                unsigned long long w0, w1, h01, h23, h45, h67;
                asm("mov.b64 %0,{%1,%1};" : "=l"(w0) : "f"(wv.x));
                asm("mov.b64 %0,{%1,%1};" : "=l"(w1) : "f"(wv.y));
                unsigned a = hb + (unsigned)(kk * HS_STRIDE) * 4u;
                asm volatile("ld.shared.v2.u64 {%0,%1},[%2];" : "=l"(h01), "=l"(h23) : "r"(a));
                asm volatile("ld.shared.v2.u64 {%0,%1},[%2];" : "=l"(h45), "=l"(h67) : "r"(a + 16));
                asm("fma.rn.f32x2 %0,%1,%2,%0;" : "+l"(a0[0]) : "l"(h01), "l"(w0));
                asm("fma.rn.f32x2 %0,%1,%2,%0;" : "+l"(a1[0]) : "l"(h01), "l"(w1));
                asm("fma.rn.f32x2 %0,%1,%2,%0;" : "+l"(a0[1]) : "l"(h23), "l"(w0));
                asm("fma.rn.f32x2 %0,%1,%2,%0;" : "+l"(a1[1]) : "l"(h23), "l"(w1));
                asm("fma.rn.f32x2 %0,%1,%2,%0;" : "+l"(a0[2]) : "l"(h45), "l"(w0));
                asm("fma.rn.f32x2 %0,%1,%2,%0;" : "+l"(a1[2]) : "l"(h45), "l"(w1));
                asm("fma.rn.f32x2 %0,%1,%2,%0;" : "+l"(a0[3]) : "l"(h67), "l"(w0));
                asm("fma.rn.f32x2 %0,%1,%2,%0;" : "+l"(a1[3]) : "l"(h67), "l"(w1));
            }
            if (c + 1 < NCHUNK) {
                __syncthreads();          // buf (c+1)&1 free (last read 2 chunks ago)
                float* dst = hs + ((c + 1) & 1) * (2 * KC * HS_STRIDE);
                #pragma unroll
                for (int i = 0; i < 4; ++i) {
                    int krow = kr + i * 16;
                    int half = krow >> 5, kl = krow & 31;
                    *(float4*)(dst + half * (KC * HS_STRIDE) + kl * HS_STRIDE + rf * 4) = pf[i];
                }
            }
        }

        // combine the two k-halves through smem (scratch aliases buf0: idle in chunk 7)
        unsigned long long* red = (unsigned long long*)hs;
        if (kh == 1) {
            #pragma unroll
            for (int i = 0; i < 4; ++i) {
                red[(tid - 128) * 8 + i]     = a0[i];
                red[(tid - 128) * 8 + 4 + i] = a1[i];
            }
        }
        __syncthreads();
        if (kh == 0) {
            #pragma unroll
            for (int i = 0; i < 4; ++i) {
                unsigned long long p0 = red[tid * 8 + i], p1 = red[tid * 8 + 4 + i];
                asm("add.rn.f32x2 %0,%0,%1;" : "+l"(a0[i]) : "l"(p0));
                asm("add.rn.f32x2 %0,%0,%1;" : "+l"(a1[i]) : "l"(p1));
            }
            float r0v[8], r1v[8];
            #pragma unroll
            for (int i = 0; i < 4; ++i) {
                asm("mov.b64 {%0,%1},%2;" : "=f"(r0v[2*i]), "=f"(r0v[2*i+1]) : "l"(a0[i]));
                asm("mov.b64 {%0,%1},%2;" : "=f"(r1v[2*i]), "=f"(r1v[2*i+1]) : "l"(a1[i]));
            }
            const int rbase = row0 + rg * 8;
            #pragma unroll
            for (int j = 0; j < 8; ++j) {
                float xv = x[(rbase + j) * S + t];
                r0v[j] = tanhf(r0v[j] + xv * wx0 + bb0);
                r1v[j] = tanhf(r1v[j] + xv * wx1 + bb1);
            }
            float* o0 = hout + (col0 + 2 * cg) * Bsz + rbase;
            float* o1 = o0 + Bsz;
            *(float4*)(o0)     = make_float4(r0v[0], r0v[1], r0v[2], r0v[3]);
            *(float4*)(o0 + 4) = make_float4(r0v[4], r0v[5], r0v[6], r0v[7]);
            *(float4*)(o1)     = make_float4(r1v[0], r1v[1], r1v[2], r1v[3]);
            *(float4*)(o1 + 4) = make_float4(r1v[4], r1v[5], r1v[6], r1v[7]);
        }
        grid_barrier(t == S - 1 ? 0u : (unsigned)(t + 2));
    }

    // Final projection + softmax (col-block-0 CTAs, 64 rows each). hT final in buf 0.
    if (cb == 0) {
        for (int idx = tid; idx < OUTD * H; idx += NTHR) sm[idx] = W_oh[idx];
        __syncthreads();
        const float* hT = g_hT[0];
        int r = tid & 63, g = tid >> 6;           // 4 c-groups of 128
        float p[OUTD];
        #pragma unroll
        for (int od = 0; od < OUTD; ++od) p[od] = 0.f;
        for (int c2 = g * 128; c2 < g * 128 + 128; ++c2) {
            float hv = hT[c2 * Bsz + row0 + r];   // coalesced along r
            #pragma unroll
            for (int od = 0; od < OUTD; ++od) p[od] += hv * sm[od * H + c2];
        }
        float* part = sm + OUTD * H;
        #pragma unroll
        for (int od = 0; od < OUTD; ++od) part[tid * OUTD + od] = p[od];
        __syncthreads();
        if (tid < 64) {
            float o[OUTD];
            #pragma unroll
            for (int od = 0; od < OUTD; ++od)
                o[od] = part[tid * OUTD + od] + part[(64 + tid) * OUTD + od]
                      + part[(128 + tid) * OUTD + od] + part[(192 + tid) * OUTD + od]
                      + b_oh[od];
            float m = o[0];
            #pragma unroll
            for (int od = 1; od < OUTD; ++od) m = fmaxf(m, o[od]);
            float ssum = 0.f;
            #pragma unroll
            for (int od = 0; od < OUTD; ++od) { o[od] = expf(o[od] - m); ssum += o[od]; }
            float inv = 1.0f / ssum;
            #pragma unroll
            for (int od = 0; od < OUTD; ++od)
                out[(row0 + tid) * OUTD + od] = o[od] * inv;
        }
    }
}

extern "C" void kernel_launch(void* const* d_in, const int* in_sizes, int n_in,
                              void* d_out, int out_size) {
    const float* x    = (const float*)d_in[0];
    const float* W_hx = (const float*)d_in[1];
    const float* b_hx = (const float*)d_in[2];
    const float* W_hh = (const float*)d_in[3];
    const float* b_hh = (const float*)d_in[4];
    const float* W_oh = (const float*)d_in[5];
    const float* b_oh = (const float*)d_in[6];
    float* out = (float*)d_out;

    cudaFuncSetAttribute(rnn_kernel, cudaFuncAttributeMaxDynamicSharedMemorySize, SMEM_BYTES);
    rnn_kernel<<<dim3(GX, GY, 1), NTHR, SMEM_BYTES>>>(x, W_hx, b_hx, W_hh, b_hh, W_oh, b_oh, out);
}